// round 2
// baseline (speedup 1.0000x reference)
#include <cuda_runtime.h>
#include <cuda_bf16.h>
#include <mma.h>

using namespace nvcuda;

// Problem constants (B=2, C=32, X=96)
#define BATCH        2
#define CCH          32
#define XD           96
#define SPATIAL      884736      // 96^3
#define XSTRIDE      9216        // 96*96
#define CH_STRIDE    884736      // X^3
#define B_STRIDE     28311552    // 32 * X^3
#define XPAIRS       48
#define CHUNKS_PER_B 13824       // 48 * 288  (288 = 9216/32)
#define GPB          76          // blocks per batch
#define NWARPS       8
#define TILE_LD      72          // 64 voxels + 8 pad (multiple of 8 for wmma)

// Accumulators (scratch via __device__ globals; no allocation allowed)
__device__ float g_A[BATCH][CCH * CCH];
__device__ float g_vol[BATCH][CCH];
__device__ float g_sym;

__global__ void init_kernel() {
    int i = threadIdx.x;
    for (int j = i; j < CCH * CCH; j += 256) { g_A[0][j] = 0.f; g_A[1][j] = 0.f; }
    if (i < CCH) { g_vol[0][i] = 0.f; g_vol[1][i] = 0.f; }
    if (i == 0) g_sym = 0.f;
}

__device__ __forceinline__ void softmax32(float (&p)[32]) {
    float m = p[0];
    #pragma unroll
    for (int c = 1; c < 32; c++) m = fmaxf(m, p[c]);
    float s = 0.f;
    #pragma unroll
    for (int c = 0; c < 32; c++) { p[c] = __expf(p[c] - m); s += p[c]; }
    float inv = __fdividef(1.0f, s);
    #pragma unroll
    for (int c = 0; c < 32; c++) p[c] *= inv;
}

__global__ __launch_bounds__(256, 1) void main_kernel(const float* __restrict__ logits) {
    __shared__ __align__(256) __nv_bfloat16 tiles[NWARPS][CCH * TILE_LD];

    const int tid  = threadIdx.x;
    const int warp = tid >> 5;
    const int lane = tid & 31;
    const int b    = blockIdx.x / GPB;
    const int blk  = blockIdx.x % GPB;
    const int wg   = blk * NWARPS + warp;       // warp id within this batch's grid
    const int wstep = GPB * NWARPS;

    const float* Lb = logits + b * B_STRIDE;
    __nv_bfloat16* tile = tiles[warp];

    wmma::fragment<wmma::accumulator, 16, 16, 16, float> acc[2][2];
    #pragma unroll
    for (int i = 0; i < 2; i++)
        #pragma unroll
        for (int j = 0; j < 2; j++)
            wmma::fill_fragment(acc[i][j], 0.0f);

    float vacc[32];
    #pragma unroll
    for (int c = 0; c < 32; c++) vacc[c] = 0.f;
    float symacc = 0.f;

    for (int chunk = wg; chunk < CHUNKS_PER_B; chunk += wstep) {
        const int x = chunk / 288;
        const int s = (chunk - x * 288) * 32 + lane;
        const float* L1 = Lb + x * XSTRIDE + s;
        const float* L2 = Lb + (XD - 1 - x) * XSTRIDE + s;

        float p1[32], p2[32];
        #pragma unroll
        for (int c = 0; c < 32; c++) p1[c] = L1[c * CH_STRIDE];
        #pragma unroll
        for (int c = 0; c < 32; c++) p2[c] = L2[c * CH_STRIDE];

        softmax32(p1);
        softmax32(p2);

        // symmetry: pair contributes 2 * sum_c |p1[c] - p2[(c+16)&31]| (x2 in finalize)
        float sv = 0.f;
        #pragma unroll
        for (int c = 0; c < 32; c++) sv += fabsf(p1[c] - p2[(c + 16) & 31]);
        symacc += sv;

        // volume partial
        #pragma unroll
        for (int c = 0; c < 32; c++) vacc[c] += p1[c] + p2[c];

        // stage bf16 tile: [channel][voxel], 64 voxels (p1 cols 0..31, p2 cols 32..63)
        #pragma unroll
        for (int c = 0; c < 32; c++) {
            tile[c * TILE_LD + lane]      = __float2bfloat16(p1[c]);
            tile[c * TILE_LD + 32 + lane] = __float2bfloat16(p2[c]);
        }
        __syncwarp();

        // Gram accumulate: A += P * P^T via tensor cores
        #pragma unroll
        for (int ci = 0; ci < 2; ci++) {
            #pragma unroll
            for (int kk = 0; kk < 4; kk++) {
                wmma::fragment<wmma::matrix_a, 16, 16, 16, __nv_bfloat16, wmma::row_major> fa;
                wmma::load_matrix_sync(fa, tile + ci * 16 * TILE_LD + kk * 16, TILE_LD);
                #pragma unroll
                for (int di = 0; di < 2; di++) {
                    wmma::fragment<wmma::matrix_b, 16, 16, 16, __nv_bfloat16, wmma::col_major> fb;
                    wmma::load_matrix_sync(fb, tile + di * 16 * TILE_LD + kk * 16, TILE_LD);
                    wmma::mma_sync(acc[ci][di], fa, fb, acc[ci][di]);
                }
            }
        }
        __syncwarp();
    }

    // ---- flush Gram: fragments -> smem (as fp32, ld=32) -> global atomics ----
    float* ftile = reinterpret_cast<float*>(tile);
    #pragma unroll
    for (int ci = 0; ci < 2; ci++)
        #pragma unroll
        for (int di = 0; di < 2; di++)
            wmma::store_matrix_sync(ftile + ci * 16 * 32 + di * 16, acc[ci][di], 32,
                                    wmma::mem_row_major);
    __syncwarp();
    #pragma unroll 4
    for (int r = 0; r < 32; r++)
        atomicAdd(&g_A[b][r * 32 + lane], ftile[r * 32 + lane]);

    // ---- flush volume ----
    #pragma unroll
    for (int c = 0; c < 32; c++) {
        float v = vacc[c];
        #pragma unroll
        for (int o = 16; o > 0; o >>= 1) v += __shfl_xor_sync(0xFFFFFFFF, v, o);
        if (lane == 0) atomicAdd(&g_vol[b][c], v);
    }

    // ---- flush sym ----
    #pragma unroll
    for (int o = 16; o > 0; o >>= 1) symacc += __shfl_xor_sync(0xFFFFFFFF, symacc, o);
    if (lane == 0) atomicAdd(&g_sym, symacc);
}

__global__ void finalize_kernel(const float* __restrict__ age,
                                const float* __restrict__ wy,
                                const float* __restrict__ wo,
                                const float* __restrict__ vmy,
                                const float* __restrict__ vmo,
                                const float* __restrict__ vsy,
                                const float* __restrict__ vso,
                                const float* __restrict__ prior,
                                float* __restrict__ out) {
    const int c = threadIdx.x;   // 32 threads, lane = row
    const float a0 = fminf(fmaxf(age[0] * 0.01f, 0.f), 1.f);
    const float a1 = fminf(fmaxf(age[1] * 0.01f, 0.f), 1.f);

    // weighted adjacency row
    float aw[32], pr[32];
    float rsum = 0.f, psum = 0.f;
    #pragma unroll
    for (int d = 0; d < 32; d++) {
        float wyv = wy[c * 32 + d], wov = wo[c * 32 + d];
        float w0 = (1.f - a0) * wyv + a0 * wov;
        float w1 = (1.f - a1) * wyv + a1 * wov;
        float v = (d == c) ? 0.f
                           : 0.5f * (g_A[0][c * 32 + d] * w0 + g_A[1][c * 32 + d] * w1);
        aw[d] = v; rsum += v;
        float pv = (d == c) ? 0.f : prior[c * 32 + d];
        pr[d] = pv; psum += pv;
    }
    const float rinv = 1.f / fmaxf(rsum, 1e-8f);
    const float pinv = 1.f / fmaxf(psum, 1e-8f);
    float part = 0.f;
    #pragma unroll
    for (int d = 0; d < 32; d++) part += fabsf(aw[d] * rinv - pr[d] * pinv);
    #pragma unroll
    for (int o = 16; o > 0; o >>= 1) part += __shfl_xor_sync(0xFFFFFFFF, part, o);
    const float loss_adj = part * (1.f / 1024.f);

    // volume smooth-L1
    float vpart = 0.f;
    {
        float mean = (1.f - a0) * vmy[c] + a0 * vmo[c];
        float std  = (1.f - a0) * vsy[c] + a0 * vso[c];
        float x = (g_vol[0][c] - mean) / (std + 1e-6f);
        float ax = fabsf(x);
        vpart += (ax < 1.f) ? 0.5f * x * x : ax - 0.5f;
    }
    {
        float mean = (1.f - a1) * vmy[c] + a1 * vmo[c];
        float std  = (1.f - a1) * vsy[c] + a1 * vso[c];
        float x = (g_vol[1][c] - mean) / (std + 1e-6f);
        float ax = fabsf(x);
        vpart += (ax < 1.f) ? 0.5f * x * x : ax - 0.5f;
    }
    #pragma unroll
    for (int o = 16; o > 0; o >>= 1) vpart += __shfl_xor_sync(0xFFFFFFFF, vpart, o);
    const float loss_vol = vpart * (1.f / 64.f);

    // symmetry (x2: each pair counted in both flip directions)
    const float loss_sym = 2.f * g_sym / 56623104.f;   // B*C*X^3

    if (c == 0)
        out[0] = 0.15f * loss_adj + 0.2f * loss_vol + 0.05f * loss_sym;
}

extern "C" void kernel_launch(void* const* d_in, const int* in_sizes, int n_in,
                              void* d_out, int out_size) {
    const float* logits = (const float*)d_in[0];
    const float* age    = (const float*)d_in[1];
    const float* wy     = (const float*)d_in[2];
    const float* wo     = (const float*)d_in[3];
    const float* vmy    = (const float*)d_in[4];
    const float* vmo    = (const float*)d_in[5];
    const float* vsy    = (const float*)d_in[6];
    const float* vso    = (const float*)d_in[7];
    const float* prior  = (const float*)d_in[8];
    float* out = (float*)d_out;

    init_kernel<<<1, 256>>>();
    main_kernel<<<BATCH * GPB, 256>>>(logits);
    finalize_kernel<<<1, 32>>>(age, wy, wo, vmy, vmo, vsy, vso, prior, out);
}

// round 3
// speedup vs baseline: 1.0741x; 1.0741x over previous
#include <cuda_runtime.h>
#include <cuda_bf16.h>
#include <mma.h>

using namespace nvcuda;

// Problem constants (B=2, C=32, X=96)
#define BATCH        2
#define CCH          32
#define XD           96
#define XSTRIDE      9216        // 96*96
#define CH_STRIDE    884736      // X^3
#define B_STRIDE     28311552    // 32 * X^3
#define CHUNKS_PER_B 13824       // 48 * 288  (288 = 9216/32)
#define GPB          222         // blocks per batch (grid = 444 = 3*148, wave-aligned)
#define NWARPS       4
#define TILE_LD      72          // 64 voxels + 8 pad (multiple of 8 for wmma)

// Accumulators (scratch via __device__ globals; no allocation allowed)
__device__ float g_A[BATCH][CCH * CCH];
__device__ float g_vol[BATCH][CCH];
__device__ float g_sym;

__global__ void init_kernel() {
    int i = threadIdx.x;
    for (int j = i; j < CCH * CCH; j += 256) { g_A[0][j] = 0.f; g_A[1][j] = 0.f; }
    if (i < CCH) { g_vol[0][i] = 0.f; g_vol[1][i] = 0.f; }
    if (i == 0) g_sym = 0.f;
}

__device__ __forceinline__ void softmax32(float (&p)[32]) {
    float m = p[0];
    #pragma unroll
    for (int c = 1; c < 32; c++) m = fmaxf(m, p[c]);
    float s = 0.f;
    #pragma unroll
    for (int c = 0; c < 32; c++) { p[c] = __expf(p[c] - m); s += p[c]; }
    float inv = __fdividef(1.0f, s);
    #pragma unroll
    for (int c = 0; c < 32; c++) p[c] *= inv;
}

__global__ __launch_bounds__(128, 3) void main_kernel(const float* __restrict__ logits) {
    __shared__ __align__(256) __nv_bfloat16 tiles[NWARPS][CCH * TILE_LD];

    const int tid  = threadIdx.x;
    const int warp = tid >> 5;
    const int lane = tid & 31;
    const int b    = blockIdx.x / GPB;
    const int blk  = blockIdx.x % GPB;
    const int wg   = blk * NWARPS + warp;       // warp id within this batch's grid
    const int wstep = GPB * NWARPS;

    const float* Lb = logits + b * B_STRIDE;
    __nv_bfloat16* tile = tiles[warp];

    wmma::fragment<wmma::accumulator, 16, 16, 16, float> acc[2][2];
    #pragma unroll
    for (int i = 0; i < 2; i++)
        #pragma unroll
        for (int j = 0; j < 2; j++)
            wmma::fill_fragment(acc[i][j], 0.0f);

    float vacc[32];
    #pragma unroll
    for (int c = 0; c < 32; c++) vacc[c] = 0.f;
    float symacc = 0.f;

    for (int chunk = wg; chunk < CHUNKS_PER_B; chunk += wstep) {
        const int x = chunk / 288;
        const int s = (chunk - x * 288) * 32 + lane;
        const float* L1 = Lb + x * XSTRIDE + s;
        const float* L2 = Lb + (XD - 1 - x) * XSTRIDE + s;

        float p1[32], p2[32];
        #pragma unroll
        for (int c = 0; c < 32; c++) p1[c] = L1[c * CH_STRIDE];
        #pragma unroll
        for (int c = 0; c < 32; c++) p2[c] = L2[c * CH_STRIDE];

        softmax32(p1);
        softmax32(p2);

        // symmetry: pair contributes 2 * sum_c |p1[c] - p2[(c+16)&31]| (x2 in finalize)
        float sv = 0.f;
        #pragma unroll
        for (int c = 0; c < 32; c++) sv += fabsf(p1[c] - p2[(c + 16) & 31]);
        symacc += sv;

        // volume partial
        #pragma unroll
        for (int c = 0; c < 32; c++) vacc[c] += p1[c] + p2[c];

        // stage bf16 tile: [channel][voxel-pair], packed bf16x2 at even cols.
        // Column layout: p1 of this lane's voxel at col 2*lane, p2 at 2*lane+1.
        // This is a pure permutation of the K dimension -> Gram result unchanged.
        #pragma unroll
        for (int c = 0; c < 32; c++) {
            __nv_bfloat162 pk = __floats2bfloat162_rn(p1[c], p2[c]);
            *reinterpret_cast<__nv_bfloat162*>(tile + c * TILE_LD + 2 * lane) = pk;
        }
        __syncwarp();

        // Gram accumulate: A += P * P^T via tensor cores
        #pragma unroll
        for (int ci = 0; ci < 2; ci++) {
            #pragma unroll
            for (int kk = 0; kk < 4; kk++) {
                wmma::fragment<wmma::matrix_a, 16, 16, 16, __nv_bfloat16, wmma::row_major> fa;
                wmma::load_matrix_sync(fa, tile + ci * 16 * TILE_LD + kk * 16, TILE_LD);
                #pragma unroll
                for (int di = 0; di < 2; di++) {
                    wmma::fragment<wmma::matrix_b, 16, 16, 16, __nv_bfloat16, wmma::col_major> fb;
                    wmma::load_matrix_sync(fb, tile + di * 16 * TILE_LD + kk * 16, TILE_LD);
                    wmma::mma_sync(acc[ci][di], fa, fb, acc[ci][di]);
                }
            }
        }
        __syncwarp();
    }

    // ---- flush Gram: fragments -> smem (as fp32, ld=32) -> global atomics ----
    float* ftile = reinterpret_cast<float*>(tile);
    #pragma unroll
    for (int ci = 0; ci < 2; ci++)
        #pragma unroll
        for (int di = 0; di < 2; di++)
            wmma::store_matrix_sync(ftile + ci * 16 * 32 + di * 16, acc[ci][di], 32,
                                    wmma::mem_row_major);
    __syncwarp();
    #pragma unroll 4
    for (int r = 0; r < 32; r++)
        atomicAdd(&g_A[b][r * 32 + lane], ftile[r * 32 + lane]);

    // ---- flush volume ----
    #pragma unroll
    for (int c = 0; c < 32; c++) {
        float v = vacc[c];
        #pragma unroll
        for (int o = 16; o > 0; o >>= 1) v += __shfl_xor_sync(0xFFFFFFFF, v, o);
        if (lane == 0) atomicAdd(&g_vol[b][c], v);
    }

    // ---- flush sym ----
    #pragma unroll
    for (int o = 16; o > 0; o >>= 1) symacc += __shfl_xor_sync(0xFFFFFFFF, symacc, o);
    if (lane == 0) atomicAdd(&g_sym, symacc);
}

__global__ void finalize_kernel(const float* __restrict__ age,
                                const float* __restrict__ wy,
                                const float* __restrict__ wo,
                                const float* __restrict__ vmy,
                                const float* __restrict__ vmo,
                                const float* __restrict__ vsy,
                                const float* __restrict__ vso,
                                const float* __restrict__ prior,
                                float* __restrict__ out) {
    const int c = threadIdx.x;   // 32 threads, lane = row
    const float a0 = fminf(fmaxf(age[0] * 0.01f, 0.f), 1.f);
    const float a1 = fminf(fmaxf(age[1] * 0.01f, 0.f), 1.f);

    // weighted adjacency row
    float aw[32], pr[32];
    float rsum = 0.f, psum = 0.f;
    #pragma unroll
    for (int d = 0; d < 32; d++) {
        float wyv = wy[c * 32 + d], wov = wo[c * 32 + d];
        float w0 = (1.f - a0) * wyv + a0 * wov;
        float w1 = (1.f - a1) * wyv + a1 * wov;
        float v = (d == c) ? 0.f
                           : 0.5f * (g_A[0][c * 32 + d] * w0 + g_A[1][c * 32 + d] * w1);
        aw[d] = v; rsum += v;
        float pv = (d == c) ? 0.f : prior[c * 32 + d];
        pr[d] = pv; psum += pv;
    }
    const float rinv = 1.f / fmaxf(rsum, 1e-8f);
    const float pinv = 1.f / fmaxf(psum, 1e-8f);
    float part = 0.f;
    #pragma unroll
    for (int d = 0; d < 32; d++) part += fabsf(aw[d] * rinv - pr[d] * pinv);
    #pragma unroll
    for (int o = 16; o > 0; o >>= 1) part += __shfl_xor_sync(0xFFFFFFFF, part, o);
    const float loss_adj = part * (1.f / 1024.f);

    // volume smooth-L1
    float vpart = 0.f;
    {
        float mean = (1.f - a0) * vmy[c] + a0 * vmo[c];
        float std  = (1.f - a0) * vsy[c] + a0 * vso[c];
        float x = (g_vol[0][c] - mean) / (std + 1e-6f);
        float ax = fabsf(x);
        vpart += (ax < 1.f) ? 0.5f * x * x : ax - 0.5f;
    }
    {
        float mean = (1.f - a1) * vmy[c] + a1 * vmo[c];
        float std  = (1.f - a1) * vsy[c] + a1 * vso[c];
        float x = (g_vol[1][c] - mean) / (std + 1e-6f);
        float ax = fabsf(x);
        vpart += (ax < 1.f) ? 0.5f * x * x : ax - 0.5f;
    }
    #pragma unroll
    for (int o = 16; o > 0; o >>= 1) vpart += __shfl_xor_sync(0xFFFFFFFF, vpart, o);
    const float loss_vol = vpart * (1.f / 64.f);

    // symmetry (x2: each pair counted in both flip directions)
    const float loss_sym = 2.f * g_sym / 56623104.f;   // B*C*X^3

    if (c == 0)
        out[0] = 0.15f * loss_adj + 0.2f * loss_vol + 0.05f * loss_sym;
}

extern "C" void kernel_launch(void* const* d_in, const int* in_sizes, int n_in,
                              void* d_out, int out_size) {
    const float* logits = (const float*)d_in[0];
    const float* age    = (const float*)d_in[1];
    const float* wy     = (const float*)d_in[2];
    const float* wo     = (const float*)d_in[3];
    const float* vmy    = (const float*)d_in[4];
    const float* vmo    = (const float*)d_in[5];
    const float* vsy    = (const float*)d_in[6];
    const float* vso    = (const float*)d_in[7];
    const float* prior  = (const float*)d_in[8];
    float* out = (float*)d_out;

    init_kernel<<<1, 256>>>();
    main_kernel<<<BATCH * GPB, 128>>>(logits);
    finalize_kernel<<<1, 32>>>(age, wy, wo, vmy, vmo, vsy, vso, prior, out);
}